// round 16
// baseline (speedup 1.0000x reference)
#include <cuda_runtime.h>
#include <cuda_fp16.h>

#define DIM 300
#define C 16
#define NPTS 1048576u   // 2^20
#define PLANE (DIM * DIM)

#define BB_PER_SLOT 177                 // build blocks per slot (128 thr, 4 texels/thr)
#define BUILD_BLOCKS (3 * BB_PER_SLOT)  // 531
#define SLOT_THREADS (BB_PER_SLOT * 128)   // 22656
#define SAMPLE_BLOCKS_PER_SLAB 8192

// Pair-interleaved fp16 scratch (x-neighbor pre-clamped at build time).
// Plane block (slot o, y, x): 32 halves = 16 ch of __half2{ v[y][x], v[y][min(x+1,DIM-1)] }.
// Line  block (slot o, j):    32 halves = 16 ch of __half2{ v[j],    v[min(j+1,DIM-1)] }.
// slot o=0 -> (plane_yz, line_x), o=1 -> (plane_xz, line_y), o=2 -> (plane_xy, line_z)
__device__ __align__(128) __half g_plane_p[3 * PLANE * 2 * C];   // 17.28 MB
__device__ __align__(128) __half g_line_p[3 * DIM * 2 * C];      // 57.6 KB
__device__ int g_cnt[3];

__global__ void reset_kernel() {
    if (threadIdx.x < 3) g_cnt[threadIdx.x] = 0;
}

__device__ __forceinline__ float4 combine(uint4 r0, uint4 r1, uint4 lr,
                                          float wx, float wy, float wl) {
    const __half2* h0 = reinterpret_cast<const __half2*>(&r0);
    const __half2* h1 = reinterpret_cast<const __half2*>(&r1);
    const __half2* hl = reinterpret_cast<const __half2*>(&lr);
    float res[4];
#pragma unroll
    for (int i = 0; i < 4; i++) {
        float2 f0 = __half22float2(h0[i]);   // (v[y0][x0], v[y0][x1])
        float2 f1 = __half22float2(h1[i]);   // (v[y1][x0], v[y1][x1])
        float2 fl2 = __half22float2(hl[i]);  // (l[j0], l[j1])
        float vx0 = fmaf(wx, f0.y - f0.x, f0.x);
        float vx1 = fmaf(wx, f1.y - f1.x, f1.x);
        float v   = fmaf(wy, vx1 - vx0, vx0);
        float lv  = fmaf(wl, fl2.y - fl2.x, fl2.x);
        res[i] = v * lv;
    }
    return make_float4(res[0], res[1], res[2], res[3]);
}

// Fused kernel: blocks [0, 531) build scratch (177 blocks per slot, releasing
// g_cnt[slot] when done); blocks [531, 531+3*8192) are R10-style samplers for
// slab o, each spin-waiting on g_cnt[o] before sampling. Wave-1 (lowest ~1332
// ids) contains all build blocks, so spinners cannot starve the builds.
__global__ void __launch_bounds__(128, 9) fused_kernel(
    const float2* __restrict__ coords_plane,   // (3, N)
    const float2* __restrict__ coords_line,    // (3, N)
    const float* __restrict__ pxy, const float* __restrict__ pyz,
    const float* __restrict__ pxz,
    const float* __restrict__ lx, const float* __restrict__ ly,
    const float* __restrict__ lz,
    float4* __restrict__ out)                  // (3, N, 4) float4
{
    int bid = blockIdx.x;
    int tid = threadIdx.x;

    if (bid < BUILD_BLOCKS) {
        // ---------------- build role ----------------
        int slot = bid / BB_PER_SLOT;
        int blk = bid - slot * BB_PER_SLOT;
        const float* psrc = (slot == 0) ? pyz : (slot == 1) ? pxz : pxy;
        const float* lsrc = (slot == 0) ? lx : (slot == 1) ? ly : lz;

#pragma unroll
        for (int k = 0; k < 4; k++) {
            int idx = blk * 128 + tid + k * SLOT_THREADS;
            if (idx < PLANE) {
                int pos = idx;                   // y*DIM + x
                int x = pos % DIM;
                int dx = (x < DIM - 1) ? 1 : 0;
                union { __half2 h2[16]; uint4 u[4]; } pk;
#pragma unroll
                for (int c = 0; c < C; c++) {
                    float a = __ldg(&psrc[c * PLANE + pos]);
                    float b = __ldg(&psrc[c * PLANE + pos + dx]);
                    pk.h2[c] = __floats2half2_rn(a, b);
                }
                uint4* dst = reinterpret_cast<uint4*>(
                    g_plane_p + ((size_t)slot * PLANE + pos) * 2 * C);
#pragma unroll
                for (int j = 0; j < 4; j++) dst[j] = pk.u[j];
            } else if (idx < PLANE + DIM) {
                int pos = idx - PLANE;
                int dx = (pos < DIM - 1) ? 1 : 0;
                union { __half2 h2[16]; uint4 u[4]; } pk;
#pragma unroll
                for (int c = 0; c < C; c++) {
                    float a = __ldg(&lsrc[c * DIM + pos]);
                    float b = __ldg(&lsrc[c * DIM + pos + dx]);
                    pk.h2[c] = __floats2half2_rn(a, b);
                }
                uint4* dst = reinterpret_cast<uint4*>(
                    g_line_p + ((size_t)slot * DIM + pos) * 2 * C);
#pragma unroll
                for (int j = 0; j < 4; j++) dst[j] = pk.u[j];
            }
        }
        __syncthreads();
        if (tid == 0) {
            __threadfence();                       // release scratch writes
            atomicAdd(&g_cnt[slot], 1);
        }
        return;
    }

    // ---------------- sample role (R10 body, slab o fixed) ----------------
    int sid = bid - BUILD_BLOCKS;
    unsigned o = (unsigned)(sid >> 13);            // / 8192
    unsigned blk = (unsigned)(sid & 8191);

    if (tid == 0) {
        while (*(volatile int*)&g_cnt[o] < BB_PER_SLOT) __nanosleep(64);
        __threadfence();                           // acquire
    }
    __syncthreads();

    unsigned po = (o == 2u) ? 0u : o + 1u;
    const float2* cp = coords_plane + po * NPTS;
    const float2* cl = coords_line + o * NPTS;
    float4* outp = out + (size_t)o * NPTS * 4;
    unsigned pbase0 = o * (unsigned)(PLANE * 4);
    unsigned lbase0 = o * (unsigned)(DIM * 4);

    unsigned warp = blk * 4u + ((unsigned)tid >> 5);   // < N/32
    unsigned lane = (unsigned)tid & 31u;

    unsigned n = warp * 32u + lane;

    float2 pc = __ldg(&cp[n]);
    float2 lc = __ldg(&cl[n]);

    const float S = 0.5f * (DIM - 1);
    float ix = fmaf(pc.x, S, S);
    float iy = fmaf(pc.y, S, S);
    int x0 = (int)ix;                 // trunc == floor (coords in [-1,1) => ix >= 0)
    int y0 = (int)iy;
    float wx = ix - (float)x0;
    float wy = iy - (float)y0;
    unsigned pb = pbase0 + (unsigned)(y0 * DIM + x0) * 4u;

    float iyl = fmaf(lc.y, S, S);
    int j0 = (int)iyl;
    float wl = iyl - (float)j0;
    unsigned lb = lbase0 + (unsigned)j0 * 4u;

    unsigned q = lane & 3u;
    unsigned sub = lane >> 2;                 // point-within-slot 0..7
    unsigned outbase = warp * 128u + lane;    // float4 units; +32 per slot

    const uint4* P = reinterpret_cast<const uint4*>(g_plane_p);
    const uint4* L = reinterpret_cast<const uint4*>(g_line_p);

    // ---- slots 0,1 ----
    unsigned s0 = sub, s1 = 8u + sub;
    unsigned p0 = __shfl_sync(0xffffffffu, pb, s0) + q;
    unsigned l0 = __shfl_sync(0xffffffffu, lb, s0) + q;
    float wx0 = __shfl_sync(0xffffffffu, wx, s0);
    float wy0 = __shfl_sync(0xffffffffu, wy, s0);
    float wl0 = __shfl_sync(0xffffffffu, wl, s0);
    unsigned p1 = __shfl_sync(0xffffffffu, pb, s1) + q;
    unsigned l1 = __shfl_sync(0xffffffffu, lb, s1) + q;
    float wx1 = __shfl_sync(0xffffffffu, wx, s1);
    float wy1 = __shfl_sync(0xffffffffu, wy, s1);
    float wl1 = __shfl_sync(0xffffffffu, wl, s1);

    uint4 a0 = __ldcg(P + p0);
    uint4 a1 = __ldcg(P + p0 + DIM * 4);
    uint4 b0 = __ldcg(P + p1);
    uint4 b1 = __ldcg(P + p1 + DIM * 4);
    uint4 la = __ldg(L + l0);
    uint4 lbv = __ldg(L + l1);

    __stcs(&outp[outbase], combine(a0, a1, la, wx0, wy0, wl0));
    __stcs(&outp[outbase + 32u], combine(b0, b1, lbv, wx1, wy1, wl1));

    // ---- slots 2,3 ----
    unsigned s2 = 16u + sub, s3 = 24u + sub;
    unsigned p2 = __shfl_sync(0xffffffffu, pb, s2) + q;
    unsigned l2 = __shfl_sync(0xffffffffu, lb, s2) + q;
    float wx2 = __shfl_sync(0xffffffffu, wx, s2);
    float wy2 = __shfl_sync(0xffffffffu, wy, s2);
    float wl2 = __shfl_sync(0xffffffffu, wl, s2);
    unsigned p3 = __shfl_sync(0xffffffffu, pb, s3) + q;
    unsigned l3 = __shfl_sync(0xffffffffu, lb, s3) + q;
    float wx3 = __shfl_sync(0xffffffffu, wx, s3);
    float wy3 = __shfl_sync(0xffffffffu, wy, s3);
    float wl3 = __shfl_sync(0xffffffffu, wl, s3);

    uint4 c0 = __ldcg(P + p2);
    uint4 c1 = __ldcg(P + p2 + DIM * 4);
    uint4 d0 = __ldcg(P + p3);
    uint4 d1 = __ldcg(P + p3 + DIM * 4);
    uint4 lc2 = __ldg(L + l2);
    uint4 ld3 = __ldg(L + l3);

    __stcs(&outp[outbase + 64u], combine(c0, c1, lc2, wx2, wy2, wl2));
    __stcs(&outp[outbase + 96u], combine(d0, d1, ld3, wx3, wy3, wl3));
}

extern "C" void kernel_launch(void* const* d_in, const int* in_sizes, int n_in,
                              void* d_out, int out_size) {
    const float* coords_plane = (const float*)d_in[0];
    const float* coords_line  = (const float*)d_in[1];
    const float* plane_xy     = (const float*)d_in[2];
    const float* plane_yz     = (const float*)d_in[3];
    const float* plane_xz     = (const float*)d_in[4];
    const float* line_x       = (const float*)d_in[5];
    const float* line_y       = (const float*)d_in[6];
    const float* line_z       = (const float*)d_in[7];
    float* out = (float*)d_out;

    reset_kernel<<<1, 32>>>();

    int grid = BUILD_BLOCKS + 3 * SAMPLE_BLOCKS_PER_SLAB;   // 25107
    fused_kernel<<<grid, 128>>>(
        reinterpret_cast<const float2*>(coords_plane),
        reinterpret_cast<const float2*>(coords_line),
        plane_xy, plane_yz, plane_xz, line_x, line_y, line_z,
        reinterpret_cast<float4*>(out));
}

// round 17
// speedup vs baseline: 1.2941x; 1.2941x over previous
#include <cuda_runtime.h>
#include <cuda_fp16.h>

#define DIM 300
#define C 16
#define NPTS 1048576u   // 2^20
#define PLANE (DIM * DIM)

// Pair-interleaved fp16 scratch (x-neighbor pre-clamped at build time).
// Plane block (slot o, y, x): 32 halves = 16 ch of __half2{ v[y][x], v[y][min(x+1,DIM-1)] }.
// Line  block (slot o, j):    32 halves = 16 ch of __half2{ v[j],    v[min(j+1,DIM-1)] }.
// slot o=0 -> (plane_yz, line_x), o=1 -> (plane_xz, line_y), o=2 -> (plane_xy, line_z)
__device__ __align__(128) __half g_plane_p[3 * PLANE * 2 * C];   // 17.28 MB
__device__ __align__(128) __half g_line_p[3 * DIM * 2 * C];      // 57.6 KB

__global__ void transpose_kernel(const float* __restrict__ pxy,
                                 const float* __restrict__ pyz,
                                 const float* __restrict__ pxz,
                                 const float* __restrict__ lx,
                                 const float* __restrict__ ly,
                                 const float* __restrict__ lz) {
    int id = blockIdx.x * blockDim.x + threadIdx.x;
    if (id < 3 * PLANE) {
        int p = id / PLANE;
        int pos = id - p * PLANE;       // y*DIM + x
        int x = pos % DIM;
        int dx = (x < DIM - 1) ? 1 : 0;
        const float* src = (p == 0) ? pyz : (p == 1) ? pxz : pxy;
        union { __half2 h2[16]; uint4 u[4]; } pk;
#pragma unroll
        for (int c = 0; c < C; c++) {
            float a = __ldg(&src[c * PLANE + pos]);
            float b = __ldg(&src[c * PLANE + pos + dx]);
            pk.h2[c] = __floats2half2_rn(a, b);
        }
        uint4* dst = reinterpret_cast<uint4*>(g_plane_p + (size_t)(p * PLANE + pos) * 2 * C);
#pragma unroll
        for (int j = 0; j < 4; j++) dst[j] = pk.u[j];
    } else if (id < 3 * PLANE + 3 * DIM) {
        int r = id - 3 * PLANE;
        int p = r / DIM;
        int pos = r - p * DIM;
        int dx = (pos < DIM - 1) ? 1 : 0;
        const float* src = (p == 0) ? lx : (p == 1) ? ly : lz;
        union { __half2 h2[16]; uint4 u[4]; } pk;
#pragma unroll
        for (int c = 0; c < C; c++) {
            float a = __ldg(&src[c * DIM + pos]);
            float b = __ldg(&src[c * DIM + pos + dx]);
            pk.h2[c] = __floats2half2_rn(a, b);
        }
        uint4* dst = reinterpret_cast<uint4*>(g_line_p + (size_t)(p * DIM + pos) * 2 * C);
#pragma unroll
        for (int j = 0; j < 4; j++) dst[j] = pk.u[j];
    }
}

__device__ __forceinline__ float4 combine(uint4 r0, uint4 r1, uint4 lr,
                                          float wx, float wy, float wl) {
    const __half2* h0 = reinterpret_cast<const __half2*>(&r0);
    const __half2* h1 = reinterpret_cast<const __half2*>(&r1);
    const __half2* hl = reinterpret_cast<const __half2*>(&lr);
    float res[4];
#pragma unroll
    for (int i = 0; i < 4; i++) {
        float2 f0 = __half22float2(h0[i]);   // (v[y0][x0], v[y0][x1])
        float2 f1 = __half22float2(h1[i]);   // (v[y1][x0], v[y1][x1])
        float2 fl2 = __half22float2(hl[i]);  // (l[j0], l[j1])
        float vx0 = fmaf(wx, f0.y - f0.x, f0.x);
        float vx1 = fmaf(wx, f1.y - f1.x, f1.x);
        float v   = fmaf(wy, vx1 - vx0, vx0);
        float lv  = fmaf(wl, fl2.y - fl2.x, fl2.x);
        res[i] = v * lv;
    }
    return make_float4(res[0], res[1], res[2], res[3]);
}

// Warp-cooperative (R10 structure) with PACKED shfl broadcasts:
//   packed_a = (y0*DIM+x0) | (j0 << 17)          (addr: 1 shfl, was 2)
//   packed_w = fx16(wx) | (fx16(wy) << 16)       (weights: 1 shfl, was 2)
//   wl                                            (1 shfl, fp32 exact)
// o is warp-uniform (warp = 32 consecutive points in one slab), so o-base
// terms are not broadcast. 12 shfl/warp instead of 20 on the L1TEX pipe.
// No clamps: coords strictly in [-1,1); "+1" x/j neighbor pre-clamped in scratch.
__global__ void __launch_bounds__(128, 9) sample_kernel(
    const float2* __restrict__ coords_plane,   // (3, N)
    const float2* __restrict__ coords_line,    // (3, N)
    float4* __restrict__ out)                  // (3, N, 4) float4
{
    unsigned warp = (blockIdx.x * 128u + threadIdx.x) >> 5;   // < 3N/32
    unsigned lane = threadIdx.x & 31u;

    // ---- decode this lane's point ----
    unsigned mypt = warp * 32u + lane;        // < 3N
    unsigned o = mypt >> 20;                  // warp-uniform
    unsigned n = mypt & (NPTS - 1u);
    unsigned po = (o == 2u) ? 0u : o + 1u;

    float2 pc = __ldg(&coords_plane[po * NPTS + n]);
    float2 lc = __ldg(&coords_line[o * NPTS + n]);

    const float S = 0.5f * (DIM - 1);
    float ix = fmaf(pc.x, S, S);
    float iy = fmaf(pc.y, S, S);
    int x0 = (int)ix;                 // trunc == floor (ix >= 0)
    int y0 = (int)iy;
    float wx = ix - (float)x0;
    float wy = iy - (float)y0;

    float iyl = fmaf(lc.y, S, S);
    int j0 = (int)iyl;
    float wl = iyl - (float)j0;

    // pack: pos (17b) | j0 (9b);  fx16 weights (error <= 2^-16, negligible)
    unsigned packed_a = (unsigned)(y0 * DIM + x0) | ((unsigned)j0 << 17);
    unsigned packed_w = (unsigned)(wx * 65536.0f) |
                        ((unsigned)(wy * 65536.0f) << 16);

    unsigned pbase0 = o * (unsigned)(PLANE * 4);   // warp-uniform
    unsigned lbase0 = o * (unsigned)(DIM * 4);

    unsigned q = lane & 3u;
    unsigned sub = lane >> 2;                 // point-within-slot 0..7
    unsigned outbase = warp * 128u + lane;    // float4 units; +32 per slot

    const uint4* P = reinterpret_cast<const uint4*>(g_plane_p);
    const uint4* L = reinterpret_cast<const uint4*>(g_line_p);
    const float INV64K = 1.0f / 65536.0f;

    // ---- slots 0,1 ----
    unsigned s0 = sub, s1 = 8u + sub;
    unsigned ua0 = __shfl_sync(0xffffffffu, packed_a, s0);
    unsigned uw0 = __shfl_sync(0xffffffffu, packed_w, s0);
    float wl0 = __shfl_sync(0xffffffffu, wl, s0);
    unsigned ua1 = __shfl_sync(0xffffffffu, packed_a, s1);
    unsigned uw1 = __shfl_sync(0xffffffffu, packed_w, s1);
    float wl1 = __shfl_sync(0xffffffffu, wl, s1);

    unsigned p0 = pbase0 + (ua0 & 0x1FFFFu) * 4u + q;
    unsigned l0 = lbase0 + (ua0 >> 17) * 4u + q;
    unsigned p1 = pbase0 + (ua1 & 0x1FFFFu) * 4u + q;
    unsigned l1 = lbase0 + (ua1 >> 17) * 4u + q;

    uint4 a0 = __ldcg(P + p0);
    uint4 a1 = __ldcg(P + p0 + DIM * 4);
    uint4 b0 = __ldcg(P + p1);
    uint4 b1 = __ldcg(P + p1 + DIM * 4);
    uint4 la = __ldg(L + l0);
    uint4 lbv = __ldg(L + l1);

    float wx0 = (float)(uw0 & 0xFFFFu) * INV64K;
    float wy0 = (float)(uw0 >> 16) * INV64K;
    float wx1 = (float)(uw1 & 0xFFFFu) * INV64K;
    float wy1 = (float)(uw1 >> 16) * INV64K;

    __stcs(&out[outbase], combine(a0, a1, la, wx0, wy0, wl0));
    __stcs(&out[outbase + 32u], combine(b0, b1, lbv, wx1, wy1, wl1));

    // ---- slots 2,3 ----
    unsigned s2 = 16u + sub, s3 = 24u + sub;
    unsigned ua2 = __shfl_sync(0xffffffffu, packed_a, s2);
    unsigned uw2 = __shfl_sync(0xffffffffu, packed_w, s2);
    float wl2 = __shfl_sync(0xffffffffu, wl, s2);
    unsigned ua3 = __shfl_sync(0xffffffffu, packed_a, s3);
    unsigned uw3 = __shfl_sync(0xffffffffu, packed_w, s3);
    float wl3 = __shfl_sync(0xffffffffu, wl, s3);

    unsigned p2 = pbase0 + (ua2 & 0x1FFFFu) * 4u + q;
    unsigned l2 = lbase0 + (ua2 >> 17) * 4u + q;
    unsigned p3 = pbase0 + (ua3 & 0x1FFFFu) * 4u + q;
    unsigned l3 = lbase0 + (ua3 >> 17) * 4u + q;

    uint4 c0 = __ldcg(P + p2);
    uint4 c1 = __ldcg(P + p2 + DIM * 4);
    uint4 d0 = __ldcg(P + p3);
    uint4 d1 = __ldcg(P + p3 + DIM * 4);
    uint4 lc2 = __ldg(L + l2);
    uint4 ld3 = __ldg(L + l3);

    float wx2 = (float)(uw2 & 0xFFFFu) * INV64K;
    float wy2 = (float)(uw2 >> 16) * INV64K;
    float wx3 = (float)(uw3 & 0xFFFFu) * INV64K;
    float wy3 = (float)(uw3 >> 16) * INV64K;

    __stcs(&out[outbase + 64u], combine(c0, c1, lc2, wx2, wy2, wl2));
    __stcs(&out[outbase + 96u], combine(d0, d1, ld3, wx3, wy3, wl3));
}

extern "C" void kernel_launch(void* const* d_in, const int* in_sizes, int n_in,
                              void* d_out, int out_size) {
    const float* coords_plane = (const float*)d_in[0];
    const float* coords_line  = (const float*)d_in[1];
    const float* plane_xy     = (const float*)d_in[2];
    const float* plane_yz     = (const float*)d_in[3];
    const float* plane_xz     = (const float*)d_in[4];
    const float* line_x       = (const float*)d_in[5];
    const float* line_y       = (const float*)d_in[6];
    const float* line_z       = (const float*)d_in[7];
    float* out = (float*)d_out;

    {
        int total = 3 * PLANE + 3 * DIM;
        int block = 256;
        int grid = (total + block - 1) / block;
        transpose_kernel<<<grid, block>>>(plane_xy, plane_yz, plane_xz,
                                          line_x, line_y, line_z);
    }
    {
        unsigned threads_total = 3u * NPTS;        // one lane decodes one point
        int block = 128;
        int grid = (int)(threads_total / block);   // 24576
        sample_kernel<<<grid, block>>>(
            reinterpret_cast<const float2*>(coords_plane),
            reinterpret_cast<const float2*>(coords_line),
            reinterpret_cast<float4*>(out));
    }
}